// round 8
// baseline (speedup 1.0000x reference)
#include <cuda_runtime.h>
#include <cstdint>

// Fixed shapes
#define B_TOTAL   65536
#define P_DIM     41
#define L_DIM     4
#define PL        (P_DIM * L_DIM)          // 164
#define NROWS     (B_TOTAL * P_DIM)        // 2686976 rows of 4 lanes
#define THREADS   256
#define ITER      8
#define ROWS_PB   (THREADS * ITER)         // 2048
#define NBLOCKS   (NROWS / ROWS_PB)        // 1312 (exact)

__device__ float        g_partials[NBLOCKS];
__device__ unsigned int g_count = 0;       // ticket; returns to 0 every launch

// Pack (target, pred) bits for row i: byte l = (t&1) | (pred<<1). full=true also fills pred.
__device__ __forceinline__ unsigned int build_pk(const float4* __restrict__ gL,
                                                 const int4* __restrict__ gT,
                                                 int i, bool withPred)
{
    i = max(0, min(i, NROWS - 1));
    int4 tg = gT[i];
    unsigned int pk = (unsigned int)(tg.x & 1)
                    | ((unsigned int)(tg.y & 1) << 8)
                    | ((unsigned int)(tg.z & 1) << 16)
                    | ((unsigned int)(tg.w & 1) << 24);
    if (withPred) {
        int b = i / P_DIM;
        int p = i - b * P_DIM;
        float4 a0 = gL[b * 82 + p];
        float4 a1 = gL[b * 82 + 41 + p];
        if (a1.x > a0.x) pk |= 2u;
        if (a1.y > a0.y) pk |= 2u << 8;
        if (a1.z > a0.z) pk |= 2u << 16;
        if (a1.w > a0.w) pk |= 2u << 24;
    }
    return pk;
}

__global__ __launch_bounds__(THREADS)
void lace_kernel(const float* __restrict__ logits,
                 const int* __restrict__ targets,
                 float* __restrict__ out)
{
    __shared__ float warpsums[8];
    __shared__ float redsums[8];
    __shared__ bool  isLast;

    const int tid  = threadIdx.x;
    const int lane = tid & 31;
    const int blk  = blockIdx.x;

    const float4* gL = (const float4*)logits;
    const int4*   gT = (const int4*)targets;

    float sum = 0.0f;

    #pragma unroll
    for (int it = 0; it < ITER; ++it) {
        const int i = blk * ROWS_PB + it * THREADS + tid;   // always < NROWS
        const int b = i / P_DIM;
        const int p = i - b * P_DIM;

        // Coalesced loads: consecutive lanes -> consecutive rows
        float4 v0 = gL[b * 82 + p];          // class 0, lanes l=0..3
        float4 v1 = gL[b * 82 + 41 + p];     // class 1
        int4   tg = gT[i];                   // targets contiguous per row

        // pk: per-l byte, bit0 = target, bit1 = pred (argmax ties -> class 0)
        unsigned int pk = (unsigned int)(tg.x & 1)
                        | ((unsigned int)(tg.y & 1) << 8)
                        | ((unsigned int)(tg.z & 1) << 16)
                        | ((unsigned int)(tg.w & 1) << 24);
        if (v1.x > v0.x) pk |= 2u;
        if (v1.y > v0.y) pk |= 2u << 8;
        if (v1.z > v0.z) pk |= 2u << 16;
        if (v1.w > v0.w) pk |= 2u << 24;

        // Neighbor exchange in P via warp shuffles
        unsigned int pkm1 = __shfl_up_sync(0xffffffffu, pk, 1);
        unsigned int pkm2 = __shfl_up_sync(0xffffffffu, pk, 2);
        unsigned int pkp1 = __shfl_down_sync(0xffffffffu, pk, 1);
        unsigned int pkp2 = __shfl_down_sync(0xffffffffu, pk, 2);

        // Warp-edge lanes rebuild from global (L1/L2 hits; pred needed only for m1)
        if (lane == 0)  pkm1 = build_pk(gL, gT, i - 1, true);
        if (lane <= 1)  pkm2 = build_pk(gL, gT, i - 2, false);
        if (lane == 31) pkp1 = build_pk(gL, gT, i + 1, false);
        if (lane >= 30) pkp2 = build_pk(gL, gT, i + 2, false);

        const float L0[4] = {v0.x, v0.y, v0.z, v0.w};
        const float L1[4] = {v1.x, v1.y, v1.z, v1.w};

        #pragma unroll
        for (int l = 0; l < 4; ++l) {
            int sh = l * 8;
            int t0   = (pk   >> sh) & 1;
            int tm1  = (pkm1 >> sh) & 1;
            int tm2  = (pkm2 >> sh) & 1;
            int tp1  = (pkp1 >> sh) & 1;
            int tp2  = (pkp2 >> sh) & 1;
            int pr   = (pk   >> (sh + 1)) & 1;
            int prm1 = (pkm1 >> (sh + 1)) & 1;

            // softplus CE (C=2): loss = z + log(1 + exp(-|d|)), d = l_other - l_target
            float d = t0 ? (L0[l] - L1[l]) : (L1[l] - L0[l]);
            float z = fmaxf(d, 0.0f);
            float loss = z + __logf(1.0f + __expf(d - z - z));

            // boundary weight, edge-masked (binary targets: |a-b| == a^b)
            int w1 = ((p > 0)         ? (t0 ^ tm1) : 0)
                   + ((p < P_DIM - 1) ? (tp1 ^ t0) : 0);
            int w2 = ((p > 1)         ? (t0 ^ tm2) : 0)
                   + ((p < P_DIM - 2) ? (tp2 ^ t0) : 0);
            float w = 1.0f + (float)w1 + 0.5f * (float)w2;

            float tot = loss * w;
            if (p > 0 && pr != prm1) tot += 0.001f;
            sum += tot;
        }
    }

    // warp reduce (8 warps) -> block partial
    #pragma unroll
    for (int o = 16; o > 0; o >>= 1)
        sum += __shfl_down_sync(0xffffffffu, sum, o);
    if (lane == 0) warpsums[tid >> 5] = sum;
    __syncthreads();

    if (tid == 0) {
        float bs = 0.0f;
        #pragma unroll
        for (int k = 0; k < 8; ++k) bs += warpsums[k];
        g_partials[blk] = bs;
        __threadfence();
        unsigned int old = atomicAdd(&g_count, 1u);
        isLast = (old == NBLOCKS - 1);
    }
    __syncthreads();

    // last block: deterministic fixed-order reduction of 1312 partials
    if (isLast) {
        float s = 0.0f;
        #pragma unroll
        for (int k = 0; k < 6; ++k) {
            int idx = tid + k * THREADS;
            if (idx < NBLOCKS) s += g_partials[idx];
        }
        #pragma unroll
        for (int o = 16; o > 0; o >>= 1)
            s += __shfl_down_sync(0xffffffffu, s, o);
        if (lane == 0) redsums[tid >> 5] = s;
        __syncthreads();
        if (tid == 0) {
            float t = 0.0f;
            #pragma unroll
            for (int k = 0; k < 8; ++k) t += redsums[k];
            out[0] = t * (1.0f / ((float)B_TOTAL * (float)P_DIM * (float)L_DIM));
            g_count = 0;   // reset for next graph replay
        }
    }
}

extern "C" void kernel_launch(void* const* d_in, const int* in_sizes, int n_in,
                              void* d_out, int out_size)
{
    const float* logits  = (const float*)d_in[0];
    const int*   targets = (const int*)d_in[1];
    float*       out     = (float*)d_out;

    lace_kernel<<<NBLOCKS, THREADS>>>(logits, targets, out);
}

// round 11
// speedup vs baseline: 1.6026x; 1.6026x over previous
#include <cuda_runtime.h>
#include <cstdint>

// Fixed shapes
#define B_TOTAL   65536
#define P_DIM     41
#define NROWS     (B_TOTAL * P_DIM)        // 2686976 rows of 4 lanes (L=4)
#define THREADS   256
#define WARPS_PB  8
#define USEFUL    28                        // useful rows per warp-chunk (lanes 2..29)
#define ITER      6
#define SPAN      (USEFUL * ITER)           // 168 rows per warp
#define ROWS_PB   (SPAN * WARPS_PB)         // 1344 rows per block
#define NBLOCKS   ((NROWS + ROWS_PB - 1) / ROWS_PB)   // 2000

__device__ float        g_partials[NBLOCKS];
__device__ unsigned int g_count = 0;        // ticket; returns to 0 every launch

__global__ __launch_bounds__(THREADS, 4)
void lace_kernel(const float* __restrict__ logits,
                 const int* __restrict__ targets,
                 float* __restrict__ out)
{
    __shared__ float warpsums[WARPS_PB];
    __shared__ float redsums[WARPS_PB];
    __shared__ bool  isLast;

    const int tid   = threadIdx.x;
    const int lane  = tid & 31;
    const int wid   = tid >> 5;
    const int gwarp = blockIdx.x * WARPS_PB + wid;

    const float4* __restrict__ gL = (const float4*)logits;   // [b][c][p] rows of 4 floats; 82 f4/batch
    const int4*   __restrict__ gT = (const int4*)targets;    // 1 int4 per row

    const bool laneOK = (lane >= 2 && lane <= 29);

    float acc     = 0.0f;
    int   connAcc = 0;

    #pragma unroll
    for (int c = 0; c < ITER; ++c) {
        const int rl = gwarp * SPAN + c * USEFUL + lane - 2;   // logical row (halo: -2..+1 past chunk)
        const int r  = min(max(rl, 0), NROWS - 1);             // clamped row (OOB only on halo/tail lanes)
        const bool valid = laneOK && (rl < NROWS);

        const unsigned bu = (unsigned)r / 41u;
        const int b = (int)bu;
        const int p = r - b * 41;
        const int idx0 = r + b * 41;                           // = b*82 + p

        // Coalesced wide loads: consecutive lanes -> consecutive rows
        const float4 v0 = gL[idx0];            // class 0
        const float4 v1 = gL[idx0 + 41];       // class 1
        const int4   tg = gT[r];

        const float ne0 = v0.x - v1.x, ne1 = v0.y - v1.y;
        const float ne2 = v0.z - v1.z, ne3 = v0.w - v1.w;

        // Pack per-l bits into one word: bit6 = target, bit7 = pred (sign of ne: l1>l0 <=> ne<0)
        unsigned pa = __byte_perm((unsigned)tg.x, (unsigned)tg.y, 0x0040);
        unsigned pb = __byte_perm((unsigned)tg.z, (unsigned)tg.w, 0x0040);
        unsigned sT = __byte_perm(pa, pb, 0x5410);             // target (0/1) in byte.bit0
        unsigned qa = __byte_perm(__float_as_uint(ne0), __float_as_uint(ne1), 0x0073);
        unsigned qb = __byte_perm(__float_as_uint(ne2), __float_as_uint(ne3), 0x0073);
        unsigned sP = __byte_perm(qa, qb, 0x5410);             // sign bit in byte.bit7
        unsigned pk = (sT << 6) | (sP & 0x80808080u);

        // Batch-boundary-clamped shuffle sources: clamping to self makes xor terms vanish
        int sm1 = (p == 0)          ? lane : lane - 1;
        int sm2 = (p <= 1)          ? lane : lane - 2;
        int sp1 = (p == P_DIM - 1)  ? lane : lane + 1;
        int sp2 = (p >= P_DIM - 2)  ? lane : lane + 2;

        unsigned pkm1 = __shfl_sync(0xffffffffu, pk, sm1);
        unsigned pkm2 = __shfl_sync(0xffffffffu, pk, sm2);
        unsigned pkp1 = __shfl_sync(0xffffffffu, pk, sp1);
        unsigned pkp2 = __shfl_sync(0xffffffffu, pk, sp2);

        unsigned xm1 = pk ^ pkm1;
        unsigned xm2 = pk ^ pkm2;
        unsigned xp1 = pk ^ pkp1;
        unsigned xp2 = pk ^ pkp2;

        // Connectivity: pred-xor vs p-1 (bit7/byte), masked by validity, integer accumulate
        unsigned maskC = valid ? 0x80808080u : 0u;
        connAcc += __popc(xm1 & maskC);

        // Weight bytes: value = 2w-2 in [0,6] per byte
        unsigned w1 = ((xm1 >> 6) & 0x01010101u) + ((xp1 >> 6) & 0x01010101u);
        unsigned w2 = ((xm2 >> 6) & 0x01010101u) + ((xp2 >> 6) & 0x01010101u);
        unsigned wb = w1 + w1 + w2;

        // mis = t ^ pred, at bit7 of each byte
        unsigned misW = (pk << 1) ^ pk;

        const float vf = valid ? 1.0f : 0.0f;
        const float hv = valid ? 0.5f : 0.0f;

        const float nes[4] = {ne0, ne1, ne2, ne3};
        #pragma unroll
        for (int l = 0; l < 4; ++l) {
            float ae = fabsf(nes[l]);
            // softplus(d) = mis*|ne| + log(1 + exp(-|ne|)); |d| == |ne|, d>0 <=> mis
            float ex  = __expf(-ae);
            float sp  = __logf(1.0f + ex);
            float z   = ((misW >> (8 * l + 7)) & 1u) ? ae : 0.0f;
            float loss = z + sp;
            float fb  = (float)((wb >> (8 * l)) & 0xFFu);      // 2w-2
            float wf  = fmaf(fb, hv, vf);                      // = valid * w
            acc = fmaf(loss, wf, acc);
        }
    }

    acc = fmaf(0.001f, (float)connAcc, acc);

    // warp reduce -> block partial
    #pragma unroll
    for (int o = 16; o > 0; o >>= 1)
        acc += __shfl_down_sync(0xffffffffu, acc, o);
    if (lane == 0) warpsums[wid] = acc;
    __syncthreads();

    if (tid == 0) {
        float bs = 0.0f;
        #pragma unroll
        for (int k = 0; k < WARPS_PB; ++k) bs += warpsums[k];
        g_partials[blockIdx.x] = bs;
        __threadfence();
        unsigned int old = atomicAdd(&g_count, 1u);
        isLast = (old == NBLOCKS - 1);
    }
    __syncthreads();

    // last block: deterministic fixed-order reduction of all partials
    if (isLast) {
        float s = 0.0f;
        #pragma unroll
        for (int k = 0; k < (NBLOCKS + THREADS - 1) / THREADS; ++k) {
            int idx = tid + k * THREADS;
            if (idx < NBLOCKS) s += g_partials[idx];
        }
        #pragma unroll
        for (int o = 16; o > 0; o >>= 1)
            s += __shfl_down_sync(0xffffffffu, s, o);
        if (lane == 0) redsums[wid] = s;
        __syncthreads();
        if (tid == 0) {
            float t = 0.0f;
            #pragma unroll
            for (int k = 0; k < WARPS_PB; ++k) t += redsums[k];
            out[0] = t * (1.0f / ((float)B_TOTAL * (float)P_DIM * 4.0f));
            g_count = 0;   // reset for next graph replay
        }
    }
}

extern "C" void kernel_launch(void* const* d_in, const int* in_sizes, int n_in,
                              void* d_out, int out_size)
{
    const float* logits  = (const float*)d_in[0];
    const int*   targets = (const int*)d_in[1];
    float*       out     = (float*)d_out;

    lace_kernel<<<NBLOCKS, THREADS>>>(logits, targets, out);
}